// round 15
// baseline (speedup 1.0000x reference)
#include <cuda_runtime.h>
#include <cuda_bf16.h>
#include <math.h>
#include <stdint.h>

#define NB_   32
#define NC_   6
#define NIMG  384
#define NBOX  64
#define CROP_ 224
#define CPAD  228            // halo-padded crop dim (+1 offset, zeroed border)
#define IMG_H_ 512
#define IMG_W_ 1408
#define N1    (NIMG * 3136)
#define K1P   224            // conv1 K: 7 ky * (8 kx-slots * 4 ch)

// ---------------- scratch (device globals; no allocation) ----------------
__device__ float g_theta[NIMG * 6];
__device__ int   g_valid[NIMG];
__device__ __align__(16) __nv_bfloat16 g_cropsh[(size_t)NIMG * CPAD * CPAD * 4];
__device__ __align__(16) __nv_bfloat16 g_cropsl[(size_t)NIMG * CPAD * CPAD * 4];
__device__ __align__(16) __nv_bfloat16 g_h1h[(size_t)N1 * 64], g_h1l[(size_t)N1 * 64];
__device__ __align__(16) __nv_bfloat16 g_h2h[NIMG * 196 * 256], g_h2l[NIMG * 196 * 256];
__device__ __align__(16) float g_h3n[NIMG * 49 * 1024];
__device__ __align__(16) float g_k[NIMG * 50 * 1024];
__device__ __align__(16) float g_v[NIMG * 50 * 1024];
__device__ __align__(16) float g_q[NIMG * 1024];
__device__ __align__(16) float g_emb[NIMG * 1024];

__device__ __align__(16) __nv_bfloat16 g_w1h[64 * K1P],    g_w1l[64 * K1P];
__device__ __align__(16) __nv_bfloat16 g_w2h[256 * 576],   g_w2l[256 * 576];
__device__ __align__(16) __nv_bfloat16 g_w3h[1024 * 2304], g_w3l[1024 * 2304];
__device__ __align__(16) __nv_bfloat16 g_wqth[1024 * 1024], g_wqtl[1024 * 1024];
__device__ __align__(16) __nv_bfloat16 g_wkth[1024 * 1024], g_wktl[1024 * 1024];
__device__ __align__(16) __nv_bfloat16 g_wvth[1024 * 1024], g_wvtl[1024 * 1024];
__device__ __align__(16) __nv_bfloat16 g_woth[1024 * 1024], g_wotl[1024 * 1024];
__device__ __align__(16) __nv_bfloat16 g_tokh[NIMG * 50 * 1024], g_tokl[NIMG * 50 * 1024];
__device__ __align__(16) __nv_bfloat16 g_clsh[NIMG * 1024], g_clsl[NIMG * 1024];
__device__ __align__(16) __nv_bfloat16 g_ctxh[NIMG * 1024], g_ctxl[NIMG * 1024];

// ---------------- PTX helpers (sm_80-portable) ----------------
__device__ __forceinline__ uint32_t smem_u32(const void* p) {
    uint32_t a;
    asm("{ .reg .u64 t; cvta.to.shared.u64 t, %1; cvt.u32.u64 %0, t; }" : "=r"(a) : "l"(p));
    return a;
}
__device__ __forceinline__ void cp16(uint32_t saddr, const void* gptr) {
    asm volatile("cp.async.cg.shared.global [%0], [%1], 16;" :: "r"(saddr), "l"(gptr));
}
// predicated: src-size 0 -> zero-fill 16B
__device__ __forceinline__ void cp16p(uint32_t saddr, const void* gptr, int srcsz) {
    asm volatile("cp.async.cg.shared.global [%0], [%1], 16, %2;" :: "r"(saddr), "l"(gptr), "r"(srcsz));
}
#define CP_COMMIT() asm volatile("cp.async.commit_group;" ::: "memory")
#define CP_WAIT1()  asm volatile("cp.async.wait_group 1;" ::: "memory")
#define CP_WAIT0()  asm volatile("cp.async.wait_group 0;" ::: "memory")

__device__ __forceinline__ void ldsm4(uint32_t (&r)[4], uint32_t addr) {
    asm volatile("ldmatrix.sync.aligned.m8n8.x4.shared.b16 {%0,%1,%2,%3}, [%4];"
                 : "=r"(r[0]), "=r"(r[1]), "=r"(r[2]), "=r"(r[3]) : "r"(addr));
}
__device__ __forceinline__ void mma16816(float (&d)[4], const uint32_t (&a)[4],
                                         const uint32_t b0, const uint32_t b1) {
    asm volatile(
        "mma.sync.aligned.m16n8k16.row.col.f32.bf16.bf16.f32 "
        "{%0,%1,%2,%3},{%4,%5,%6,%7},{%8,%9},{%0,%1,%2,%3};"
        : "+f"(d[0]), "+f"(d[1]), "+f"(d[2]), "+f"(d[3])
        : "r"(a[0]), "r"(a[1]), "r"(a[2]), "r"(a[3]), "r"(b0), "r"(b1));
}
__device__ __forceinline__ void split_bf16(float x, __nv_bfloat16* h, __nv_bfloat16* l) {
    __nv_bfloat16 hi = __float2bfloat16(x);
    *h = hi;
    *l = __float2bfloat16(x - __bfloat162float(hi));
}

// common mma compute step on one stage
#define MMA_STAGE(st, AL_OFF, BH_OFF, BL_OFF)                                   \
    {                                                                           \
        const uint32_t aoff = (m0w + (lane & 15)) * 80 + ((lane >> 4) & 1) * 16;\
        const uint32_t boff = (n0w + (lane & 7) + ((lane & 16) >> 1)) * 80 + ((lane & 8) << 1); \
        _Pragma("unroll")                                                       \
        for (int k16 = 0; k16 < 2; k16++) {                                     \
            const uint32_t kb = k16 * 32;                                       \
            uint32_t ah[2][4], al[2][4];                                        \
            ldsm4(ah[0], (st) +            aoff + kb);                          \
            ldsm4(ah[1], (st) +            aoff + 16 * 80 + kb);                \
            ldsm4(al[0], (st) + (AL_OFF) + aoff + kb);                          \
            ldsm4(al[1], (st) + (AL_OFF) + aoff + 16 * 80 + kb);                \
            uint32_t bh[4][4], bl[4][4];                                        \
            _Pragma("unroll")                                                   \
            for (int njp = 0; njp < 4; njp++) {                                 \
                ldsm4(bh[njp], (st) + (BH_OFF) + boff + njp * 16 * 80 + kb);    \
                ldsm4(bl[njp], (st) + (BL_OFF) + boff + njp * 16 * 80 + kb);    \
            }                                                                   \
            _Pragma("unroll")                                                   \
            for (int mi = 0; mi < 2; mi++)                                      \
                _Pragma("unroll")                                               \
                for (int njp = 0; njp < 4; njp++) {                             \
                    mma16816(acc[mi][2 * njp],     ah[mi], bh[njp][0], bh[njp][1]); \
                    mma16816(acc[mi][2 * njp + 1], ah[mi], bh[njp][2], bh[njp][3]); \
                    mma16816(acc[mi][2 * njp],     ah[mi], bl[njp][0], bl[njp][1]); \
                    mma16816(acc[mi][2 * njp + 1], ah[mi], bl[njp][2], bl[njp][3]); \
                    mma16816(acc[mi][2 * njp],     al[mi], bh[njp][0], bh[njp][1]); \
                    mma16816(acc[mi][2 * njp + 1], al[mi], bh[njp][2], bh[njp][3]); \
                }                                                               \
        }                                                                       \
    }

// =============== generic split-bf16 GEMM (128x128 tile) ===============
// mode 0: fp32 out; 1: fp32+relu; 2: relu + split-bf16 out (outh/outl)
#define STG_BYTES 40960
__global__ __launch_bounds__(256, 1) void k_tgemm(
    const __nv_bfloat16* __restrict__ Ahi, const __nv_bfloat16* __restrict__ Alo,
    const __nv_bfloat16* __restrict__ Bhi, const __nv_bfloat16* __restrict__ Blo,
    int K, int OC, float* __restrict__ out,
    __nv_bfloat16* __restrict__ outh, __nv_bfloat16* __restrict__ outl, int mode) {
    extern __shared__ __align__(128) char smem[];
    const uint32_t sbase = smem_u32(smem);
    const int tid = threadIdx.x;
    const int wid = tid >> 5, lane = tid & 31;
    const int m0 = blockIdx.y * 128, n0 = blockIdx.x * 128;
    const int wm = wid & 3, wn = wid >> 2;
    const int m0w = wm * 32, n0w = wn * 64;

    float acc[2][8][4] = {};
    const int lrow = tid >> 2;
    const int lc = (tid & 3) * 16;

#define TG_LOAD(BUF, KC0) {                                                     \
        uint32_t sb = sbase + (BUF) * STG_BYTES;                                \
        _Pragma("unroll")                                                       \
        for (int h = 0; h < 2; h++) {                                           \
            int row = lrow + h * 64;                                            \
            uint32_t so = row * 80 + lc;                                        \
            size_t ga = (size_t)(m0 + row) * K + (KC0) + (lc >> 1);             \
            size_t gb = (size_t)(n0 + row) * K + (KC0) + (lc >> 1);             \
            cp16(sb + so,         Ahi + ga);                                    \
            cp16(sb + 10240 + so, Alo + ga);                                    \
            cp16(sb + 20480 + so, Bhi + gb);                                    \
            cp16(sb + 30720 + so, Blo + gb);                                    \
        }                                                                       \
        CP_COMMIT();                                                            \
    }

    const int nch = K >> 5;
    TG_LOAD(0, 0);
#pragma unroll 1
    for (int ch = 0; ch < nch; ch++) {
        if (ch + 1 < nch) { TG_LOAD((ch + 1) & 1, (ch + 1) * 32); CP_WAIT1(); }
        else              { CP_WAIT0(); }
        __syncthreads();
        const uint32_t st = sbase + (ch & 1) * STG_BYTES;
        MMA_STAGE(st, 10240, 20480, 30720);
        __syncthreads();
    }
#undef TG_LOAD

    const int rbase = m0 + m0w + (lane >> 2);
    const int cbase = n0 + n0w + ((lane & 3) << 1);
#pragma unroll
    for (int mi = 0; mi < 2; mi++)
#pragma unroll
        for (int nj = 0; nj < 8; nj++) {
            float* d = acc[mi][nj];
            int row = rbase + mi * 16;
            int col = cbase + nj * 8;
#pragma unroll
            for (int e = 0; e < 4; e++) {
                int r = row + (e >> 1) * 8;
                int c = col + (e & 1);
                float v = d[e];
                if (mode >= 1) v = fmaxf(v, 0.f);
                size_t o = (size_t)c * OC + r;
                if (mode == 2) split_bf16(v, outh + o, outl + o);
                else out[o] = v;
            }
        }
}

// =============== conv1: 64x256 tile, fused im2col-B from halo crops ===============
#define STG64 51200
__global__ __launch_bounds__(256) void k_tgemm_c1() {
    extern __shared__ __align__(128) char smem[];
    const uint32_t sbase = smem_u32(smem);
    const int tid = threadIdx.x;
    const int wid = tid >> 5, lane = tid & 31;
    const int n0 = blockIdx.x * 256;
    const int wm = wid & 1, wn = wid >> 1;     // 2 x 4 warp grid
    const int m0w = wm * 32, n0w = wn * 64;

    float acc[2][8][4] = {};

    const int n = n0 + tid;
    const int img = n / 3136, px = n - img * 3136;
    const int oy = px / 56, ox = px - oy * 56;
    const __nv_bfloat16* bsh = g_cropsh + ((size_t)(img * CPAD + oy * 4) * CPAD + ox * 4) * 4;
    const __nv_bfloat16* bsl = g_cropsl + ((size_t)(img * CPAD + oy * 4) * CPAD + ox * 4) * 4;

#define C1_LOAD(BUF, KY) {                                                      \
        uint32_t sb = sbase + (BUF) * STG64;                                    \
        if (tid < 128) {                                                        \
            int row = tid >> 1, half = tid & 1;                                 \
            uint32_t so = row * 80 + half * 32;                                 \
            size_t ga = (size_t)row * K1P + (KY) * 32 + half * 16;              \
            cp16(sb + so,        g_w1h + ga);                                   \
            cp16(sb + so + 16,   g_w1h + ga + 8);                               \
            cp16(sb + 5120 + so,      g_w1l + ga);                              \
            cp16(sb + 5120 + so + 16, g_w1l + ga + 8);                          \
        }                                                                       \
        {                                                                       \
            uint32_t so = sb + 10240 + tid * 80;                                \
            const __nv_bfloat16* ph = bsh + (size_t)(KY) * (CPAD * 4);          \
            cp16(so, ph); cp16(so + 16, ph + 8);                                \
            cp16(so + 32, ph + 16); cp16(so + 48, ph + 24);                     \
            so += 20480;                                                        \
            const __nv_bfloat16* pl = bsl + (size_t)(KY) * (CPAD * 4);          \
            cp16(so, pl); cp16(so + 16, pl + 8);                                \
            cp16(so + 32, pl + 16); cp16(so + 48, pl + 24);                     \
        }                                                                       \
        CP_COMMIT();                                                            \
    }

    C1_LOAD(0, 0);
#pragma unroll 1
    for (int ch = 0; ch < 7; ch++) {
        if (ch + 1 < 7) { C1_LOAD((ch + 1) & 1, ch + 1); CP_WAIT1(); }
        else            { CP_WAIT0(); }
        __syncthreads();
        const uint32_t st = sbase + (ch & 1) * STG64;
        MMA_STAGE(st, 5120, 10240, 30720);
        __syncthreads();
    }
#undef C1_LOAD

    const int rbase = m0w + (lane >> 2);
    const int cbase = n0 + n0w + ((lane & 3) << 1);
#pragma unroll
    for (int mi = 0; mi < 2; mi++)
#pragma unroll
        for (int nj = 0; nj < 8; nj++) {
            float* d = acc[mi][nj];
            int row = rbase + mi * 16;
            int col = cbase + nj * 8;
#pragma unroll
            for (int e = 0; e < 4; e++) {
                int r = row + (e >> 1) * 8;
                int c = col + (e & 1);
                float v = fmaxf(d[e], 0.f);
                size_t o = (size_t)c * 64 + r;
                split_bf16(v, g_h1h + o, g_h1l + o);
            }
        }
}

// =============== conv2: 128x128 tile, fused im2col-B from h1 split ===============
// B row n2 = img*196+px; k = r*64+ic; chunk ch -> r=ch/2, half=ch&1 (contiguous 64B)
__global__ __launch_bounds__(256, 1) void k_tgemm_c2() {
    extern __shared__ __align__(128) char smem[];
    const uint32_t sbase = smem_u32(smem);
    const int tid = threadIdx.x;
    const int wid = tid >> 5, lane = tid & 31;
    const int m0 = blockIdx.y * 128, n0 = blockIdx.x * 128;
    const int wm = wid & 3, wn = wid >> 2;
    const int m0w = wm * 32, n0w = wn * 64;

    float acc[2][8][4] = {};
    const int lrow = tid >> 2;
    const int lc = (tid & 3) * 16;

    size_t bbase[2];
#pragma unroll
    for (int h = 0; h < 2; h++) {
        int n = n0 + lrow + h * 64;
        int img = n / 196, px = n - img * 196;
        int oy = px / 14, ox = px - oy * 14;
        bbase[h] = ((size_t)(img * 3136 + oy * 4 * 56 + ox * 4)) * 64;
    }

#define C2_LOAD(BUF, CH) {                                                      \
        uint32_t sb = sbase + (BUF) * STG_BYTES;                                \
        int r = (CH) >> 1, half = (CH) & 1;                                     \
        int off = ((r / 3) * 56 + (r % 3)) * 64 + half * 32 + (lc >> 1);        \
        _Pragma("unroll")                                                       \
        for (int h = 0; h < 2; h++) {                                           \
            int row = lrow + h * 64;                                            \
            uint32_t so = row * 80 + lc;                                        \
            size_t ga = (size_t)(m0 + row) * 576 + (CH) * 32 + (lc >> 1);       \
            cp16(sb + so,         g_w2h + ga);                                  \
            cp16(sb + 10240 + so, g_w2l + ga);                                  \
            cp16(sb + 20480 + so, g_h1h + bbase[h] + off);                      \
            cp16(sb + 30720 + so, g_h1l + bbase[h] + off);                      \
        }                                                                       \
        CP_COMMIT();                                                            \
    }

    C2_LOAD(0, 0);
#pragma unroll 1
    for (int ch = 0; ch < 18; ch++) {
        if (ch + 1 < 18) { C2_LOAD((ch + 1) & 1, ch + 1); CP_WAIT1(); }
        else             { CP_WAIT0(); }
        __syncthreads();
        const uint32_t st = sbase + (ch & 1) * STG_BYTES;
        MMA_STAGE(st, 10240, 20480, 30720);
        __syncthreads();
    }
#undef C2_LOAD

    const int rbase = m0 + m0w + (lane >> 2);
    const int cbase = n0 + n0w + ((lane & 3) << 1);
#pragma unroll
    for (int mi = 0; mi < 2; mi++)
#pragma unroll
        for (int nj = 0; nj < 8; nj++) {
            float* d = acc[mi][nj];
            int row = rbase + mi * 16;
            int col = cbase + nj * 8;
#pragma unroll
            for (int e = 0; e < 4; e++) {
                int r = row + (e >> 1) * 8;
                int c = col + (e & 1);
                float v = fmaxf(d[e], 0.f);
                size_t o = (size_t)c * 256 + r;
                split_bf16(v, g_h2h + o, g_h2l + o);
            }
        }
}

// =============== conv3: 128x128 tile, fused im2col-B from h2 split ===============
// B row n3 = img*49+px; k = r*256+ic; chunk ch -> r=ch/8, sub=ch&7; zero at iy/ix==14
__global__ __launch_bounds__(256, 1) void k_tgemm_c3() {
    extern __shared__ __align__(128) char smem[];
    const uint32_t sbase = smem_u32(smem);
    const int tid = threadIdx.x;
    const int wid = tid >> 5, lane = tid & 31;
    const int m0 = blockIdx.y * 128, n0 = blockIdx.x * 128;
    const int wm = wid & 3, wn = wid >> 2;
    const int m0w = wm * 32, n0w = wn * 64;

    float acc[2][8][4] = {};
    const int lrow = tid >> 2;
    const int lc = (tid & 3) * 16;

    size_t bbase[2];
    int oy6[2], ox6[2];
#pragma unroll
    for (int h = 0; h < 2; h++) {
        int n = n0 + lrow + h * 64;
        int img = n / 49, px = n - img * 49;
        int oy = px / 7, ox = px - oy * 7;
        bbase[h] = ((size_t)(img * 196 + oy * 2 * 14 + ox * 2)) * 256;
        oy6[h] = (oy == 6); ox6[h] = (ox == 6);
    }

#define C3_LOAD(BUF, CH) {                                                      \
        uint32_t sb = sbase + (BUF) * STG_BYTES;                                \
        int r = (CH) >> 3, sub = (CH) & 7;                                      \
        int dy = r / 3, dx = r - dy * 3;                                        \
        int off = (dy * 14 + dx) * 256 + sub * 32 + (lc >> 1);                  \
        _Pragma("unroll")                                                       \
        for (int h = 0; h < 2; h++) {                                           \
            int row = lrow + h * 64;                                            \
            uint32_t so = row * 80 + lc;                                        \
            size_t ga = (size_t)(m0 + row) * 2304 + (CH) * 32 + (lc >> 1);      \
            cp16(sb + so,         g_w3h + ga);                                  \
            cp16(sb + 10240 + so, g_w3l + ga);                                  \
            int v = ((oy6[h] && dy == 2) || (ox6[h] && dx == 2)) ? 0 : 16;      \
            cp16p(sb + 20480 + so, g_h2h + bbase[h] + off, v);                  \
            cp16p(sb + 30720 + so, g_h2l + bbase[h] + off, v);                  \
        }                                                                       \
        CP_COMMIT();                                                            \
    }

    C3_LOAD(0, 0);
#pragma unroll 1
    for (int ch = 0; ch < 72; ch++) {
        if (ch + 1 < 72) { C3_LOAD((ch + 1) & 1, ch + 1); CP_WAIT1(); }
        else             { CP_WAIT0(); }
        __syncthreads();
        const uint32_t st = sbase + (ch & 1) * STG_BYTES;
        MMA_STAGE(st, 10240, 20480, 30720);
        __syncthreads();
    }
#undef C3_LOAD

    const int rbase = m0 + m0w + (lane >> 2);
    const int cbase = n0 + n0w + ((lane & 3) << 1);
#pragma unroll
    for (int mi = 0; mi < 2; mi++)
#pragma unroll
        for (int nj = 0; nj < 8; nj++) {
            float* d = acc[mi][nj];
            int row = rbase + mi * 16;
            int col = cbase + nj * 8;
#pragma unroll
            for (int e = 0; e < 4; e++) {
                int r = row + (e >> 1) * 8;
                int c = col + (e & 1);
                g_h3n[(size_t)c * 1024 + r] = fmaxf(d[e], 0.f);
            }
        }
}

// ---------------- weight conversions ----------------
__global__ void k_cvt_w1(const float* __restrict__ W) {
    int i = blockIdx.x * blockDim.x + threadIdx.x;
    if (i >= 64 * K1P) return;
    int oc = i / K1P, kp = i - oc * K1P;
    int ky = kp >> 5, rem = kp & 31;
    int kx = rem >> 2, ch = rem & 3;
    float v = (kx < 7 && ch < 3) ? W[oc * 147 + ch * 49 + ky * 7 + kx] : 0.f;
    split_bf16(v, g_w1h + i, g_w1l + i);
}
__global__ void k_cvt_w2(const float* __restrict__ W) {
    int i = blockIdx.x * blockDim.x + threadIdx.x;
    if (i >= 256 * 576) return;
    int oc = i / 576, kp = i - oc * 576;
    int r = kp >> 6, ic = kp & 63;
    split_bf16(W[oc * 576 + ic * 9 + r], g_w2h + i, g_w2l + i);
}
__global__ void k_cvt_w3(const float* __restrict__ W) {
    int i = blockIdx.x * blockDim.x + threadIdx.x;
    if (i >= 1024 * 2304) return;
    int oc = i / 2304, kp = i - oc * 2304;
    int r = kp >> 8, ic = kp & 255;
    split_bf16(W[(size_t)oc * 2304 + ic * 9 + r], g_w3h + i, g_w3l + i);
}
__global__ void k_cvt_wt(const float* __restrict__ W,
                         __nv_bfloat16* __restrict__ hi,
                         __nv_bfloat16* __restrict__ lo) {
    int i = blockIdx.x * blockDim.x + threadIdx.x;
    int n = i >> 10, k = i & 1023;
    split_bf16(W[k * 1024 + n], hi + i, lo + i);
}

// ---------------- crop halo zero ----------------
__global__ void k_zero_crop_halo() {
    int i = blockIdx.x * blockDim.x + threadIdx.x;
    if (i >= NIMG * 1824) return;
    int img = i / 1824, r = i - img * 1824;
    int y, x;
    if (r < 912) { int qq = r / 228; y = (qq == 0) ? 0 : 224 + qq; x = r % 228; }
    else { int r2 = r - 912; int qq = r2 / 228; x = (qq == 0) ? 0 : 224 + qq; y = r2 % 228; }
    size_t o = ((size_t)(img * CPAD + y) * CPAD + x) * 4;
    uint2 z = {0u, 0u};
    *(uint2*)(g_cropsh + o) = z;
    *(uint2*)(g_cropsl + o) = z;
}

// ---------------- stage 0: projection + affine theta ----------------
__global__ void k_setup(const float* __restrict__ pred_boxes,
                        const float* __restrict__ la_m,
                        const float* __restrict__ l2i_m,
                        const float* __restrict__ aug_m,
                        const float* __restrict__ theta_w,
                        const float* __restrict__ theta_b) {
    int t = blockIdx.x * blockDim.x + threadIdx.x;
    if (t >= NIMG) return;
    int n = t / NC_, c = t % NC_;
    int b = n / NB_, nb = n % NB_;
    const float* pb = pred_boxes + (b * NB_ + nb) * 9;

    float r[4];
#pragma unroll
    for (int i = 0; i < 4; i++) {
        float s = theta_b[i];
#pragma unroll
        for (int j = 0; j < 9; j++) s += theta_w[i * 9 + j] * pb[j];
        r[i] = tanhf(s);
    }

    const float* la = la_m + b * 16;
    float px0 = pb[0] - la[3], py0 = pb[1] - la[7], pz0 = pb[2] - la[11];
    float a00 = la[0], a01 = la[1], a02 = la[2];
    float a10 = la[4], a11 = la[5], a12 = la[6];
    float a20 = la[8], a21 = la[9], a22 = la[10];
    float det = a00 * (a11 * a22 - a12 * a21) - a01 * (a10 * a22 - a12 * a20)
              + a02 * (a10 * a21 - a11 * a20);
    float id = 1.f / det;
    float i00 = (a11 * a22 - a12 * a21) * id, i01 = (a02 * a21 - a01 * a22) * id, i02 = (a01 * a12 - a02 * a11) * id;
    float i10 = (a12 * a20 - a10 * a22) * id, i11 = (a00 * a22 - a02 * a20) * id, i12 = (a02 * a10 - a00 * a12) * id;
    float i20 = (a10 * a21 - a11 * a20) * id, i21 = (a01 * a20 - a00 * a21) * id, i22 = (a00 * a11 - a01 * a10) * id;
    float px = i00 * px0 + i01 * py0 + i02 * pz0;
    float py = i10 * px0 + i11 * py0 + i12 * pz0;
    float pz = i20 * px0 + i21 * py0 + i22 * pz0;

    const float* m = l2i_m + (b * NC_ + c) * 16;
    float qx = m[0] * px + m[1] * py + m[2] * pz + m[3];
    float qy = m[4] * px + m[5] * py + m[6] * pz + m[7];
    float qz = m[8] * px + m[9] * py + m[10] * pz + m[11];
    float z = fminf(fmaxf(qz, 1e-5f), 100000.f);
    float x = qx / z, y = qy / z;
    const float* g = aug_m + (b * NC_ + c) * 16;
    float u = g[0] * x + g[1] * y + g[2] * z + g[3];
    float v = g[4] * x + g[5] * y + g[6] * z + g[7];
    int on = (v < (float)IMG_H_) && (v >= 0.f) && (u < (float)IMG_W_) && (u >= 0.f);
    float ty = v / (float)IMG_H_ * 2.f - 1.f;
    float tx = u / (float)IMG_W_ * 2.f - 1.f;

    int idx = n * NC_ + c;
    g_theta[idx * 6 + 0] = r[0]; g_theta[idx * 6 + 1] = r[1]; g_theta[idx * 6 + 2] = tx;
    g_theta[idx * 6 + 3] = r[2]; g_theta[idx * 6 + 4] = r[3]; g_theta[idx * 6 + 5] = ty;
    g_valid[idx] = on;
}

// ---------------- stage 1: grid sample -> halo-padded split crops ----------------
__global__ void k_sample(const float* __restrict__ imgs) {
    int img = blockIdx.y;
    int p = blockIdx.x * blockDim.x + threadIdx.x;
    if (p >= CROP_ * CROP_) return;
    int oy = p / CROP_, ox = p - oy * CROP_;
    const float* th = g_theta + img * 6;
    float gx = (2.f * ox + 1.f) / CROP_ - 1.f;
    float gy = (2.f * oy + 1.f) / CROP_ - 1.f;
    float grx = th[0] * gx + th[1] * gy + th[2];
    float gry = th[3] * gx + th[4] * gy + th[5];
    float ix = ((grx + 1.f) * IMG_W_ - 1.f) * 0.5f;
    float iy = ((gry + 1.f) * IMG_H_ - 1.f) * 0.5f;
    float x0 = floorf(ix), y0 = floorf(iy);
    float wx = ix - x0, wy = iy - y0;
    float x1 = x0 + 1.f, y1 = y0 + 1.f;

    int n = img / NC_, c = img - n * NC_, b = n / NB_;
    const float* base = imgs + (size_t)(b * NC_ + c) * 3 * IMG_H_ * IMG_W_;

    int xi0 = (int)fminf(fmaxf(x0, 0.f), (float)(IMG_W_ - 1));
    int xi1 = (int)fminf(fmaxf(x1, 0.f), (float)(IMG_W_ - 1));
    int yi0 = (int)fminf(fmaxf(y0, 0.f), (float)(IMG_H_ - 1));
    int yi1 = (int)fminf(fmaxf(y1, 0.f), (float)(IMG_H_ - 1));
    float vx0 = (x0 >= 0.f && x0 <= (float)(IMG_W_ - 1)) ? 1.f : 0.f;
    float vx1 = (x1 >= 0.f && x1 <= (float)(IMG_W_ - 1)) ? 1.f : 0.f;
    float vy0 = (y0 >= 0.f && y0 <= (float)(IMG_H_ - 1)) ? 1.f : 0.f;
    float vy1 = (y1 >= 0.f && y1 <= (float)(IMG_H_ - 1)) ? 1.f : 0.f;
    float w00 = (1.f - wx) * (1.f - wy) * vx0 * vy0;
    float w01 = wx * (1.f - wy) * vx1 * vy0;
    float w10 = (1.f - wx) * wy * vx0 * vy1;
    float w11 = wx * wy * vx1 * vy1;

    union { __nv_bfloat16 b16[4]; uint2 u; } uh, ul;
#pragma unroll
    for (int ch = 0; ch < 3; ch++) {
        const float* ib = base + (size_t)ch * IMG_H_ * IMG_W_;
        float v00 = ib[yi0 * IMG_W_ + xi0];
        float v01 = ib[yi0 * IMG_W_ + xi1];
        float v10 = ib[yi1 * IMG_W_ + xi0];
        float v11 = ib[yi1 * IMG_W_ + xi1];
        float v = v00 * w00 + v01 * w01 + v10 * w10 + v11 * w11;
        split_bf16(v, &uh.b16[ch], &ul.b16[ch]);
    }
    uh.b16[3] = __float2bfloat16(0.f);
    ul.b16[3] = __float2bfloat16(0.f);
    size_t o = ((size_t)(img * CPAD + oy + 1) * CPAD + (ox + 1)) * 4;
    *(uint2*)(g_cropsh + o) = uh.u;
    *(uint2*)(g_cropsl + o) = ul.u;
}

// ---------------- tokens: split tok + contiguous cls split ----------------
__global__ void k_tokens(const float* __restrict__ pos) {
    int img = blockIdx.x;
    int d = threadIdx.x;    // 1024
    float s = 0.f;
    __nv_bfloat16* th = g_tokh + (size_t)img * 50 * 1024;
    __nv_bfloat16* tl = g_tokl + (size_t)img * 50 * 1024;
#pragma unroll 7
    for (int t = 0; t < 49; t++) {
        float v = g_h3n[((size_t)img * 49 + t) * 1024 + d];
        s += v;
        float tv = v + pos[(t + 1) * 1024 + d];
        split_bf16(tv, th + (t + 1) * 1024 + d, tl + (t + 1) * 1024 + d);
    }
    float cls = s * (1.f / 49.f) + pos[d];
    __nv_bfloat16 ch_, cl_;
    split_bf16(cls, &ch_, &cl_);
    th[d] = ch_; tl[d] = cl_;
    g_clsh[(size_t)img * 1024 + d] = ch_;
    g_clsl[(size_t)img * 1024 + d] = cl_;
}

// ---------------- attention core: scores + softmax + ctx (split out) ----------------
__global__ void k_attn(int dummy) {
    __shared__ float qs[1024];
    __shared__ float sc[50];
    __shared__ float pr[50];
    int img = blockIdx.x, tid = threadIdx.x;   // 256
    for (int i = tid; i < 1024; i += 256) qs[i] = g_q[(size_t)img * 1024 + i];
    __syncthreads();

    int wid = tid >> 5, lid = tid & 31;
    for (int t = wid; t < 50; t += 8) {
        const float* kr = g_k + ((size_t)img * 50 + t) * 1024;
        float s = 0.f;
        for (int d = lid; d < 1024; d += 32) s = fmaf(qs[d], kr[d], s);
#pragma unroll
        for (int o = 16; o > 0; o >>= 1) s += __shfl_xor_sync(0xffffffffu, s, o);
        if (lid == 0) sc[t] = s * 0.03125f;
    }
    __syncthreads();
    if (tid == 0) {
        float mx = -1e30f;
        for (int t = 0; t < 50; t++) mx = fmaxf(mx, sc[t]);
        float sum = 0.f;
        for (int t = 0; t < 50; t++) { float e = expf(sc[t] - mx); pr[t] = e; sum += e; }
        float inv = 1.f / sum;
        for (int t = 0; t < 50; t++) pr[t] *= inv;
    }
    __syncthreads();
    {
        float4 acc = {0.f, 0.f, 0.f, 0.f};
        const float4* v4 = (const float4*)(g_v + (size_t)img * 50 * 1024);
        for (int t = 0; t < 50; t++) {
            float p = pr[t];
            float4 v = v4[t * 256 + tid];
            acc.x = fmaf(p, v.x, acc.x); acc.y = fmaf(p, v.y, acc.y);
            acc.z = fmaf(p, v.z, acc.z); acc.w = fmaf(p, v.w, acc.w);
        }
        size_t o = (size_t)img * 1024 + tid * 4;
        split_bf16(acc.x, g_ctxh + o + 0, g_ctxl + o + 0);
        split_bf16(acc.y, g_ctxh + o + 1, g_ctxl + o + 1);
        split_bf16(acc.z, g_ctxh + o + 2, g_ctxl + o + 2);
        split_bf16(acc.w, g_ctxh + o + 3, g_ctxl + o + 3);
    }
}

// ---------------- momentum fusion ----------------
__global__ void k_fuse(const float* __restrict__ bdd,
                       const float* __restrict__ mom_p,
                       float* __restrict__ out) {
    int n = blockIdx.x, d = threadIdx.x;
    float mom = *mom_p;
    float e = bdd[d];
    const int order[6] = {2, 0, 1, 5, 3, 4};
#pragma unroll
    for (int i = 0; i < 6; i++) {
        int c = order[i];
        if (g_valid[n * 6 + c])
            e = mom * e + (1.f - mom) * g_emb[((size_t)(n * 6 + c)) * 1024 + d];
    }
    out[(size_t)n * 1024 + d] = e;
}

// ---------------- launch ----------------
extern "C" void kernel_launch(void* const* d_in, const int* in_sizes, int n_in,
                              void* d_out, int out_size) {
    const float* camera_imgs = (const float*)d_in[0];
    const float* pred_boxes  = (const float*)d_in[1];
    const float* img_aug     = (const float*)d_in[2];
    const float* lidar_aug   = (const float*)d_in[3];
    const float* l2i         = (const float*)d_in[4];
    const float* momentum    = (const float*)d_in[5];
    const float* bdd         = (const float*)d_in[6];
    const float* theta_w     = (const float*)d_in[7];
    const float* theta_b     = (const float*)d_in[8];
    const float* conv1       = (const float*)d_in[9];
    const float* conv2       = (const float*)d_in[10];
    const float* conv3       = (const float*)d_in[11];
    const float* pos         = (const float*)d_in[12];
    const float* wq          = (const float*)d_in[13];
    const float* wk          = (const float*)d_in[14];
    const float* wv          = (const float*)d_in[15];
    const float* wo          = (const float*)d_in[16];

    const int TG_SMEM = 2 * STG_BYTES;   // 81920
    const int C1_SMEM = 2 * STG64;       // 102400
    static int smem_set = 0;
    if (!smem_set) {
        cudaFuncSetAttribute(k_tgemm, cudaFuncAttributeMaxDynamicSharedMemorySize, TG_SMEM);
        cudaFuncSetAttribute(k_tgemm_c1, cudaFuncAttributeMaxDynamicSharedMemorySize, C1_SMEM);
        cudaFuncSetAttribute(k_tgemm_c2, cudaFuncAttributeMaxDynamicSharedMemorySize, TG_SMEM);
        cudaFuncSetAttribute(k_tgemm_c3, cudaFuncAttributeMaxDynamicSharedMemorySize, TG_SMEM);
        smem_set = 1;
    }

    __nv_bfloat16 *wqth, *wqtl, *wkth, *wktl, *wvth, *wvtl, *woth, *wotl;
    __nv_bfloat16 *tokh, *tokl, *clsh, *clsl, *ctxh, *ctxl;
    float *gq, *gk, *gv, *gemb;
    cudaGetSymbolAddress((void**)&wqth, g_wqth); cudaGetSymbolAddress((void**)&wqtl, g_wqtl);
    cudaGetSymbolAddress((void**)&wkth, g_wkth); cudaGetSymbolAddress((void**)&wktl, g_wktl);
    cudaGetSymbolAddress((void**)&wvth, g_wvth); cudaGetSymbolAddress((void**)&wvtl, g_wvtl);
    cudaGetSymbolAddress((void**)&woth, g_woth); cudaGetSymbolAddress((void**)&wotl, g_wotl);
    cudaGetSymbolAddress((void**)&tokh, g_tokh); cudaGetSymbolAddress((void**)&tokl, g_tokl);
    cudaGetSymbolAddress((void**)&clsh, g_clsh); cudaGetSymbolAddress((void**)&clsl, g_clsl);
    cudaGetSymbolAddress((void**)&ctxh, g_ctxh); cudaGetSymbolAddress((void**)&ctxl, g_ctxl);
    cudaGetSymbolAddress((void**)&gq, g_q);     cudaGetSymbolAddress((void**)&gemb, g_emb);
    cudaGetSymbolAddress((void**)&gk, g_k);     cudaGetSymbolAddress((void**)&gv, g_v);

    k_setup<<<(NIMG + 127) / 128, 128>>>(pred_boxes, lidar_aug, l2i, img_aug, theta_w, theta_b);
    k_zero_crop_halo<<<(NIMG * 1824 + 255) / 256, 256>>>();
    k_sample<<<dim3((CROP_ * CROP_ + 255) / 256, NIMG), 256>>>(camera_imgs);

    k_cvt_w1<<<(64 * K1P + 255) / 256, 256>>>(conv1);
    k_cvt_w2<<<(256 * 576 + 255) / 256, 256>>>(conv2);
    k_cvt_w3<<<(1024 * 2304 + 255) / 256, 256>>>(conv3);
    k_cvt_wt<<<(1024 * 1024) / 256, 256>>>(wq, wqth, wqtl);
    k_cvt_wt<<<(1024 * 1024) / 256, 256>>>(wk, wkth, wktl);
    k_cvt_wt<<<(1024 * 1024) / 256, 256>>>(wv, wvth, wvtl);
    k_cvt_wt<<<(1024 * 1024) / 256, 256>>>(wo, woth, wotl);

    // conv1/2/3: fully fused im2col GEMMs (no B materialization)
    k_tgemm_c1<<<N1 / 256, 256, C1_SMEM>>>();
    k_tgemm_c2<<<dim3(588, 2), 256, TG_SMEM>>>();
    k_tgemm_c3<<<dim3(147, 8), 256, TG_SMEM>>>();

    k_tokens<<<NIMG, 1024>>>(pos);

    // q projection (CLS only), K/V projections
    k_tgemm<<<dim3(3, 8), 256, TG_SMEM>>>(wqth, wqtl, clsh, clsl, 1024, 1024, gq, nullptr, nullptr, 0);
    k_tgemm<<<dim3(150, 8), 256, TG_SMEM>>>(wkth, wktl, tokh, tokl, 1024, 1024, gk, nullptr, nullptr, 0);
    k_tgemm<<<dim3(150, 8), 256, TG_SMEM>>>(wvth, wvtl, tokh, tokl, 1024, 1024, gv, nullptr, nullptr, 0);

    k_attn<<<NIMG, 256>>>(0);

    // output projection
    k_tgemm<<<dim3(3, 8), 256, TG_SMEM>>>(woth, wotl, ctxh, ctxl, 1024, 1024, gemb, nullptr, nullptr, 0);

    k_fuse<<<NBOX, 1024>>>(bdd, momentum, (float*)d_out);
}

// round 17
// speedup vs baseline: 1.4831x; 1.4831x over previous
#include <cuda_runtime.h>
#include <cuda_bf16.h>
#include <math.h>
#include <stdint.h>

#define NB_   32
#define NC_   6
#define NIMG  384
#define NBOX  64
#define CROP_ 224
#define CPAD  228            // halo-padded crop dim (+1 offset, zeroed border)
#define IMG_H_ 512
#define IMG_W_ 1408
#define N1    (NIMG * 3136)
#define K1P   224            // conv1 K: 7 ky * (8 kx-slots * 4 ch)

// ---------------- scratch (device globals; no allocation) ----------------
__device__ float g_theta[NIMG * 6];
__device__ int   g_valid[NIMG];
__device__ __align__(16) __nv_bfloat16 g_cropsh[(size_t)NIMG * CPAD * CPAD * 4];
__device__ __align__(16) __nv_bfloat16 g_cropsl[(size_t)NIMG * CPAD * CPAD * 4];
__device__ __align__(16) __nv_bfloat16 g_h1h[(size_t)N1 * 64], g_h1l[(size_t)N1 * 64];
__device__ __align__(16) __nv_bfloat16 g_h2h[NIMG * 196 * 256], g_h2l[NIMG * 196 * 256];
__device__ __align__(16) float g_h3n[NIMG * 49 * 1024];
__device__ __align__(16) float g_k[NIMG * 50 * 1024];
__device__ __align__(16) float g_v[NIMG * 50 * 1024];
__device__ __align__(16) float g_q[NIMG * 1024];
__device__ __align__(16) float g_emb[NIMG * 1024];

__device__ __align__(16) __nv_bfloat16 g_w1h[64 * K1P],    g_w1l[64 * K1P];
__device__ __align__(16) __nv_bfloat16 g_w2h[256 * 576],   g_w2l[256 * 576];
__device__ __align__(16) __nv_bfloat16 g_w3h[1024 * 2304], g_w3l[1024 * 2304];
__device__ __align__(16) __nv_bfloat16 g_wqth[1024 * 1024], g_wqtl[1024 * 1024];
__device__ __align__(16) __nv_bfloat16 g_wkth[1024 * 1024], g_wktl[1024 * 1024];
__device__ __align__(16) __nv_bfloat16 g_wvth[1024 * 1024], g_wvtl[1024 * 1024];
__device__ __align__(16) __nv_bfloat16 g_woth[1024 * 1024], g_wotl[1024 * 1024];
__device__ __align__(16) __nv_bfloat16 g_b2h[NIMG * 196 * 576],  g_b2l[NIMG * 196 * 576];
__device__ __align__(16) __nv_bfloat16 g_b3h[NIMG * 49 * 2304],  g_b3l[NIMG * 49 * 2304];
__device__ __align__(16) __nv_bfloat16 g_tokh[NIMG * 50 * 1024], g_tokl[NIMG * 50 * 1024];
__device__ __align__(16) __nv_bfloat16 g_clsh[NIMG * 1024], g_clsl[NIMG * 1024];
__device__ __align__(16) __nv_bfloat16 g_ctxh[NIMG * 1024], g_ctxl[NIMG * 1024];

// ---------------- PTX helpers (sm_80-portable) ----------------
__device__ __forceinline__ uint32_t smem_u32(const void* p) {
    uint32_t a;
    asm("{ .reg .u64 t; cvta.to.shared.u64 t, %1; cvt.u32.u64 %0, t; }" : "=r"(a) : "l"(p));
    return a;
}
__device__ __forceinline__ void cp16(uint32_t saddr, const void* gptr) {
    asm volatile("cp.async.cg.shared.global [%0], [%1], 16;" :: "r"(saddr), "l"(gptr));
}
#define CP_COMMIT() asm volatile("cp.async.commit_group;" ::: "memory")
#define CP_WAIT1()  asm volatile("cp.async.wait_group 1;" ::: "memory")
#define CP_WAIT0()  asm volatile("cp.async.wait_group 0;" ::: "memory")

__device__ __forceinline__ void ldsm4(uint32_t (&r)[4], uint32_t addr) {
    asm volatile("ldmatrix.sync.aligned.m8n8.x4.shared.b16 {%0,%1,%2,%3}, [%4];"
                 : "=r"(r[0]), "=r"(r[1]), "=r"(r[2]), "=r"(r[3]) : "r"(addr));
}
__device__ __forceinline__ void mma16816(float (&d)[4], const uint32_t (&a)[4],
                                         const uint32_t b0, const uint32_t b1) {
    asm volatile(
        "mma.sync.aligned.m16n8k16.row.col.f32.bf16.bf16.f32 "
        "{%0,%1,%2,%3},{%4,%5,%6,%7},{%8,%9},{%0,%1,%2,%3};"
        : "+f"(d[0]), "+f"(d[1]), "+f"(d[2]), "+f"(d[3])
        : "r"(a[0]), "r"(a[1]), "r"(a[2]), "r"(a[3]), "r"(b0), "r"(b1));
}
__device__ __forceinline__ void split_bf16(float x, __nv_bfloat16* h, __nv_bfloat16* l) {
    __nv_bfloat16 hi = __float2bfloat16(x);
    *h = hi;
    *l = __float2bfloat16(x - __bfloat162float(hi));
}

// common mma compute step on one stage
#define MMA_STAGE(st, AL_OFF, BH_OFF, BL_OFF)                                   \
    {                                                                           \
        const uint32_t aoff = (m0w + (lane & 15)) * 80 + ((lane >> 4) & 1) * 16;\
        const uint32_t boff = (n0w + (lane & 7) + ((lane & 16) >> 1)) * 80 + ((lane & 8) << 1); \
        _Pragma("unroll")                                                       \
        for (int k16 = 0; k16 < 2; k16++) {                                     \
            const uint32_t kb = k16 * 32;                                       \
            uint32_t ah[2][4], al[2][4];                                        \
            ldsm4(ah[0], (st) +            aoff + kb);                          \
            ldsm4(ah[1], (st) +            aoff + 16 * 80 + kb);                \
            ldsm4(al[0], (st) + (AL_OFF) + aoff + kb);                          \
            ldsm4(al[1], (st) + (AL_OFF) + aoff + 16 * 80 + kb);                \
            uint32_t bh[4][4], bl[4][4];                                        \
            _Pragma("unroll")                                                   \
            for (int njp = 0; njp < 4; njp++) {                                 \
                ldsm4(bh[njp], (st) + (BH_OFF) + boff + njp * 16 * 80 + kb);    \
                ldsm4(bl[njp], (st) + (BL_OFF) + boff + njp * 16 * 80 + kb);    \
            }                                                                   \
            _Pragma("unroll")                                                   \
            for (int mi = 0; mi < 2; mi++)                                      \
                _Pragma("unroll")                                               \
                for (int njp = 0; njp < 4; njp++) {                             \
                    mma16816(acc[mi][2 * njp],     ah[mi], bh[njp][0], bh[njp][1]); \
                    mma16816(acc[mi][2 * njp + 1], ah[mi], bh[njp][2], bh[njp][3]); \
                    mma16816(acc[mi][2 * njp],     ah[mi], bl[njp][0], bl[njp][1]); \
                    mma16816(acc[mi][2 * njp + 1], ah[mi], bl[njp][2], bl[njp][3]); \
                    mma16816(acc[mi][2 * njp],     al[mi], bh[njp][0], bh[njp][1]); \
                    mma16816(acc[mi][2 * njp + 1], al[mi], bh[njp][2], bh[njp][3]); \
                }                                                               \
        }                                                                       \
    }

// =============== generic split-bf16 GEMM (128x128 tile) ===============
// grid: (m_tiles, n_tiles) — x is M so CTAs sharing a B n-tile launch adjacently (L2 reuse)
// mode 0: fp32 out; 1: fp32+relu; 2: relu + split-bf16 out (outh/outl)
#define STG_BYTES 40960
__global__ __launch_bounds__(256, 1) void k_tgemm(
    const __nv_bfloat16* __restrict__ Ahi, const __nv_bfloat16* __restrict__ Alo,
    const __nv_bfloat16* __restrict__ Bhi, const __nv_bfloat16* __restrict__ Blo,
    int K, int OC, float* __restrict__ out,
    __nv_bfloat16* __restrict__ outh, __nv_bfloat16* __restrict__ outl, int mode) {
    extern __shared__ __align__(128) char smem[];
    const uint32_t sbase = smem_u32(smem);
    const int tid = threadIdx.x;
    const int wid = tid >> 5, lane = tid & 31;
    const int m0 = blockIdx.x * 128, n0 = blockIdx.y * 128;   // swapped: m fast
    const int wm = wid & 3, wn = wid >> 2;
    const int m0w = wm * 32, n0w = wn * 64;

    float acc[2][8][4] = {};
    const int lrow = tid >> 2;
    const int lc = (tid & 3) * 16;

#define TG_LOAD(BUF, KC0) {                                                     \
        uint32_t sb = sbase + (BUF) * STG_BYTES;                                \
        _Pragma("unroll")                                                       \
        for (int h = 0; h < 2; h++) {                                           \
            int row = lrow + h * 64;                                            \
            uint32_t so = row * 80 + lc;                                        \
            size_t ga = (size_t)(m0 + row) * K + (KC0) + (lc >> 1);             \
            size_t gb = (size_t)(n0 + row) * K + (KC0) + (lc >> 1);             \
            cp16(sb + so,         Ahi + ga);                                    \
            cp16(sb + 10240 + so, Alo + ga);                                    \
            cp16(sb + 20480 + so, Bhi + gb);                                    \
            cp16(sb + 30720 + so, Blo + gb);                                    \
        }                                                                       \
        CP_COMMIT();                                                            \
    }

    const int nch = K >> 5;
    TG_LOAD(0, 0);
#pragma unroll 1
    for (int ch = 0; ch < nch; ch++) {
        if (ch + 1 < nch) { TG_LOAD((ch + 1) & 1, (ch + 1) * 32); CP_WAIT1(); }
        else              { CP_WAIT0(); }
        __syncthreads();
        const uint32_t st = sbase + (ch & 1) * STG_BYTES;
        MMA_STAGE(st, 10240, 20480, 30720);
        __syncthreads();
    }
#undef TG_LOAD

    const int rbase = m0 + m0w + (lane >> 2);
    const int cbase = n0 + n0w + ((lane & 3) << 1);
#pragma unroll
    for (int mi = 0; mi < 2; mi++)
#pragma unroll
        for (int nj = 0; nj < 8; nj++) {
            float* d = acc[mi][nj];
            int row = rbase + mi * 16;
            int col = cbase + nj * 8;
#pragma unroll
            for (int e = 0; e < 4; e++) {
                int r = row + (e >> 1) * 8;
                int c = col + (e & 1);
                float v = d[e];
                if (mode >= 1) v = fmaxf(v, 0.f);
                size_t o = (size_t)c * OC + r;
                if (mode == 2) split_bf16(v, outh + o, outl + o);
                else out[o] = v;
            }
        }
}

// =============== conv1: 64x256 tile, fused im2col-B from halo crops ===============
#define STG64 51200
__global__ __launch_bounds__(256) void k_tgemm_c1() {
    extern __shared__ __align__(128) char smem[];
    const uint32_t sbase = smem_u32(smem);
    const int tid = threadIdx.x;
    const int wid = tid >> 5, lane = tid & 31;
    const int n0 = blockIdx.x * 256;
    const int wm = wid & 1, wn = wid >> 1;     // 2 x 4 warp grid
    const int m0w = wm * 32, n0w = wn * 64;

    float acc[2][8][4] = {};

    const int n = n0 + tid;
    const int img = n / 3136, px = n - img * 3136;
    const int oy = px / 56, ox = px - oy * 56;
    const __nv_bfloat16* bsh = g_cropsh + ((size_t)(img * CPAD + oy * 4) * CPAD + ox * 4) * 4;
    const __nv_bfloat16* bsl = g_cropsl + ((size_t)(img * CPAD + oy * 4) * CPAD + ox * 4) * 4;

#define C1_LOAD(BUF, KY) {                                                      \
        uint32_t sb = sbase + (BUF) * STG64;                                    \
        if (tid < 128) {                                                        \
            int row = tid >> 1, half = tid & 1;                                 \
            uint32_t so = row * 80 + half * 32;                                 \
            size_t ga = (size_t)row * K1P + (KY) * 32 + half * 16;              \
            cp16(sb + so,        g_w1h + ga);                                   \
            cp16(sb + so + 16,   g_w1h + ga + 8);                               \
            cp16(sb + 5120 + so,      g_w1l + ga);                              \
            cp16(sb + 5120 + so + 16, g_w1l + ga + 8);                          \
        }                                                                       \
        {                                                                       \
            uint32_t so = sb + 10240 + tid * 80;                                \
            const __nv_bfloat16* ph = bsh + (size_t)(KY) * (CPAD * 4);          \
            cp16(so, ph); cp16(so + 16, ph + 8);                                \
            cp16(so + 32, ph + 16); cp16(so + 48, ph + 24);                     \
            so += 20480;                                                        \
            const __nv_bfloat16* pl = bsl + (size_t)(KY) * (CPAD * 4);          \
            cp16(so, pl); cp16(so + 16, pl + 8);                                \
            cp16(so + 32, pl + 16); cp16(so + 48, pl + 24);                     \
        }                                                                       \
        CP_COMMIT();                                                            \
    }

    C1_LOAD(0, 0);
#pragma unroll 1
    for (int ch = 0; ch < 7; ch++) {
        if (ch + 1 < 7) { C1_LOAD((ch + 1) & 1, ch + 1); CP_WAIT1(); }
        else            { CP_WAIT0(); }
        __syncthreads();
        const uint32_t st = sbase + (ch & 1) * STG64;
        MMA_STAGE(st, 5120, 10240, 30720);
        __syncthreads();
    }
#undef C1_LOAD

    const int rbase = m0w + (lane >> 2);
    const int cbase = n0 + n0w + ((lane & 3) << 1);
#pragma unroll
    for (int mi = 0; mi < 2; mi++)
#pragma unroll
        for (int nj = 0; nj < 8; nj++) {
            float* d = acc[mi][nj];
            int row = rbase + mi * 16;
            int col = cbase + nj * 8;
#pragma unroll
            for (int e = 0; e < 4; e++) {
                int r = row + (e >> 1) * 8;
                int c = col + (e & 1);
                float v = fmaxf(d[e], 0.f);
                size_t o = (size_t)c * 64 + r;
                split_bf16(v, g_h1h + o, g_h1l + o);
            }
        }
}

// ---------------- weight conversions ----------------
__global__ void k_cvt_w1(const float* __restrict__ W) {
    int i = blockIdx.x * blockDim.x + threadIdx.x;
    if (i >= 64 * K1P) return;
    int oc = i / K1P, kp = i - oc * K1P;
    int ky = kp >> 5, rem = kp & 31;
    int kx = rem >> 2, ch = rem & 3;
    float v = (kx < 7 && ch < 3) ? W[oc * 147 + ch * 49 + ky * 7 + kx] : 0.f;
    split_bf16(v, g_w1h + i, g_w1l + i);
}
__global__ void k_cvt_w2(const float* __restrict__ W) {
    int i = blockIdx.x * blockDim.x + threadIdx.x;
    if (i >= 256 * 576) return;
    int oc = i / 576, kp = i - oc * 576;
    int r = kp >> 6, ic = kp & 63;
    split_bf16(W[oc * 576 + ic * 9 + r], g_w2h + i, g_w2l + i);
}
__global__ void k_cvt_w3(const float* __restrict__ W) {
    int i = blockIdx.x * blockDim.x + threadIdx.x;
    if (i >= 1024 * 2304) return;
    int oc = i / 2304, kp = i - oc * 2304;
    int r = kp >> 8, ic = kp & 255;
    split_bf16(W[(size_t)oc * 2304 + ic * 9 + r], g_w3h + i, g_w3l + i);
}
__global__ void k_cvt_wt(const float* __restrict__ W,
                         __nv_bfloat16* __restrict__ hi,
                         __nv_bfloat16* __restrict__ lo) {
    int i = blockIdx.x * blockDim.x + threadIdx.x;
    int n = i >> 10, k = i & 1023;
    split_bf16(W[k * 1024 + n], hi + i, lo + i);
}

// ---------------- im2col copy kernels (uint4 = 8 bf16, stride q*8) ----------------
__global__ void k_im2col2() {
    int i = blockIdx.x * blockDim.x + threadIdx.x;   // n2*72 + r*8 + q
    if (i >= NIMG * 196 * 72) return;
    int n2 = i / 72, rem = i - n2 * 72;
    int r = rem >> 3, q8 = (rem & 7) * 8;
    int img = n2 / 196, px = n2 - img * 196;
    int oy = px / 14, ox = px - oy * 14;
    int iy = oy * 4 + r / 3, ix = ox * 4 + (r % 3);
    size_t src = ((size_t)(img * 3136 + iy * 56 + ix)) * 64 + q8;
    size_t dst = (size_t)n2 * 576 + r * 64 + q8;
    *(uint4*)(g_b2h + dst) = *(const uint4*)(g_h1h + src);
    *(uint4*)(g_b2l + dst) = *(const uint4*)(g_h1l + src);
}
__global__ void k_im2col3() {
    int i = blockIdx.x * blockDim.x + threadIdx.x;   // n3*288 + r*32 + q
    if (i >= NIMG * 49 * 288) return;
    int n3 = i / 288, rem = i - n3 * 288;
    int r = rem >> 5, q8 = (rem & 31) * 8;
    int img = n3 / 49, px = n3 - img * 49;
    int oy = px / 7, ox = px - oy * 7;
    int iy = oy * 2 + r / 3, ix = ox * 2 + (r % 3);
    size_t dst = (size_t)n3 * 2304 + r * 256 + q8;
    if (iy < 14 && ix < 14) {
        size_t src = ((size_t)(img * 196 + iy * 14 + ix)) * 256 + q8;
        *(uint4*)(g_b3h + dst) = *(const uint4*)(g_h2h + src);
        *(uint4*)(g_b3l + dst) = *(const uint4*)(g_h2l + src);
    } else {
        uint4 z = {0u, 0u, 0u, 0u};
        *(uint4*)(g_b3h + dst) = z;
        *(uint4*)(g_b3l + dst) = z;
    }
}

// ---------------- crop halo zero ----------------
__global__ void k_zero_crop_halo() {
    int i = blockIdx.x * blockDim.x + threadIdx.x;
    if (i >= NIMG * 1824) return;
    int img = i / 1824, r = i - img * 1824;
    int y, x;
    if (r < 912) { int qq = r / 228; y = (qq == 0) ? 0 : 224 + qq; x = r % 228; }
    else { int r2 = r - 912; int qq = r2 / 228; x = (qq == 0) ? 0 : 224 + qq; y = r2 % 228; }
    size_t o = ((size_t)(img * CPAD + y) * CPAD + x) * 4;
    uint2 z = {0u, 0u};
    *(uint2*)(g_cropsh + o) = z;
    *(uint2*)(g_cropsl + o) = z;
}

// ---------------- stage 0: projection + affine theta ----------------
__global__ void k_setup(const float* __restrict__ pred_boxes,
                        const float* __restrict__ la_m,
                        const float* __restrict__ l2i_m,
                        const float* __restrict__ aug_m,
                        const float* __restrict__ theta_w,
                        const float* __restrict__ theta_b) {
    int t = blockIdx.x * blockDim.x + threadIdx.x;
    if (t >= NIMG) return;
    int n = t / NC_, c = t % NC_;
    int b = n / NB_, nb = n % NB_;
    const float* pb = pred_boxes + (b * NB_ + nb) * 9;

    float r[4];
#pragma unroll
    for (int i = 0; i < 4; i++) {
        float s = theta_b[i];
#pragma unroll
        for (int j = 0; j < 9; j++) s += theta_w[i * 9 + j] * pb[j];
        r[i] = tanhf(s);
    }

    const float* la = la_m + b * 16;
    float px0 = pb[0] - la[3], py0 = pb[1] - la[7], pz0 = pb[2] - la[11];
    float a00 = la[0], a01 = la[1], a02 = la[2];
    float a10 = la[4], a11 = la[5], a12 = la[6];
    float a20 = la[8], a21 = la[9], a22 = la[10];
    float det = a00 * (a11 * a22 - a12 * a21) - a01 * (a10 * a22 - a12 * a20)
              + a02 * (a10 * a21 - a11 * a20);
    float id = 1.f / det;
    float i00 = (a11 * a22 - a12 * a21) * id, i01 = (a02 * a21 - a01 * a22) * id, i02 = (a01 * a12 - a02 * a11) * id;
    float i10 = (a12 * a20 - a10 * a22) * id, i11 = (a00 * a22 - a02 * a20) * id, i12 = (a02 * a10 - a00 * a12) * id;
    float i20 = (a10 * a21 - a11 * a20) * id, i21 = (a01 * a20 - a00 * a21) * id, i22 = (a00 * a11 - a01 * a10) * id;
    float px = i00 * px0 + i01 * py0 + i02 * pz0;
    float py = i10 * px0 + i11 * py0 + i12 * pz0;
    float pz = i20 * px0 + i21 * py0 + i22 * pz0;

    const float* m = l2i_m + (b * NC_ + c) * 16;
    float qx = m[0] * px + m[1] * py + m[2] * pz + m[3];
    float qy = m[4] * px + m[5] * py + m[6] * pz + m[7];
    float qz = m[8] * px + m[9] * py + m[10] * pz + m[11];
    float z = fminf(fmaxf(qz, 1e-5f), 100000.f);
    float x = qx / z, y = qy / z;
    const float* g = aug_m + (b * NC_ + c) * 16;
    float u = g[0] * x + g[1] * y + g[2] * z + g[3];
    float v = g[4] * x + g[5] * y + g[6] * z + g[7];
    int on = (v < (float)IMG_H_) && (v >= 0.f) && (u < (float)IMG_W_) && (u >= 0.f);
    float ty = v / (float)IMG_H_ * 2.f - 1.f;
    float tx = u / (float)IMG_W_ * 2.f - 1.f;

    int idx = n * NC_ + c;
    g_theta[idx * 6 + 0] = r[0]; g_theta[idx * 6 + 1] = r[1]; g_theta[idx * 6 + 2] = tx;
    g_theta[idx * 6 + 3] = r[2]; g_theta[idx * 6 + 4] = r[3]; g_theta[idx * 6 + 5] = ty;
    g_valid[idx] = on;
}

// ---------------- stage 1: grid sample -> halo-padded split crops ----------------
__global__ void k_sample(const float* __restrict__ imgs) {
    int img = blockIdx.y;
    int p = blockIdx.x * blockDim.x + threadIdx.x;
    if (p >= CROP_ * CROP_) return;
    int oy = p / CROP_, ox = p - oy * CROP_;
    const float* th = g_theta + img * 6;
    float gx = (2.f * ox + 1.f) / CROP_ - 1.f;
    float gy = (2.f * oy + 1.f) / CROP_ - 1.f;
    float grx = th[0] * gx + th[1] * gy + th[2];
    float gry = th[3] * gx + th[4] * gy + th[5];
    float ix = ((grx + 1.f) * IMG_W_ - 1.f) * 0.5f;
    float iy = ((gry + 1.f) * IMG_H_ - 1.f) * 0.5f;
    float x0 = floorf(ix), y0 = floorf(iy);
    float wx = ix - x0, wy = iy - y0;
    float x1 = x0 + 1.f, y1 = y0 + 1.f;

    int n = img / NC_, c = img - n * NC_, b = n / NB_;
    const float* base = imgs + (size_t)(b * NC_ + c) * 3 * IMG_H_ * IMG_W_;

    int xi0 = (int)fminf(fmaxf(x0, 0.f), (float)(IMG_W_ - 1));
    int xi1 = (int)fminf(fmaxf(x1, 0.f), (float)(IMG_W_ - 1));
    int yi0 = (int)fminf(fmaxf(y0, 0.f), (float)(IMG_H_ - 1));
    int yi1 = (int)fminf(fmaxf(y1, 0.f), (float)(IMG_H_ - 1));
    float vx0 = (x0 >= 0.f && x0 <= (float)(IMG_W_ - 1)) ? 1.f : 0.f;
    float vx1 = (x1 >= 0.f && x1 <= (float)(IMG_W_ - 1)) ? 1.f : 0.f;
    float vy0 = (y0 >= 0.f && y0 <= (float)(IMG_H_ - 1)) ? 1.f : 0.f;
    float vy1 = (y1 >= 0.f && y1 <= (float)(IMG_H_ - 1)) ? 1.f : 0.f;
    float w00 = (1.f - wx) * (1.f - wy) * vx0 * vy0;
    float w01 = wx * (1.f - wy) * vx1 * vy0;
    float w10 = (1.f - wx) * wy * vx0 * vy1;
    float w11 = wx * wy * vx1 * vy1;

    union { __nv_bfloat16 b16[4]; uint2 u; } uh, ul;
#pragma unroll
    for (int ch = 0; ch < 3; ch++) {
        const float* ib = base + (size_t)ch * IMG_H_ * IMG_W_;
        float v00 = ib[yi0 * IMG_W_ + xi0];
        float v01 = ib[yi0 * IMG_W_ + xi1];
        float v10 = ib[yi1 * IMG_W_ + xi0];
        float v11 = ib[yi1 * IMG_W_ + xi1];
        float v = v00 * w00 + v01 * w01 + v10 * w10 + v11 * w11;
        split_bf16(v, &uh.b16[ch], &ul.b16[ch]);
    }
    uh.b16[3] = __float2bfloat16(0.f);
    ul.b16[3] = __float2bfloat16(0.f);
    size_t o = ((size_t)(img * CPAD + oy + 1) * CPAD + (ox + 1)) * 4;
    *(uint2*)(g_cropsh + o) = uh.u;
    *(uint2*)(g_cropsl + o) = ul.u;
}

// ---------------- tokens: split tok + contiguous cls split ----------------
__global__ void k_tokens(const float* __restrict__ pos) {
    int img = blockIdx.x;
    int d = threadIdx.x;    // 1024
    float s = 0.f;
    __nv_bfloat16* th = g_tokh + (size_t)img * 50 * 1024;
    __nv_bfloat16* tl = g_tokl + (size_t)img * 50 * 1024;
#pragma unroll 7
    for (int t = 0; t < 49; t++) {
        float v = g_h3n[((size_t)img * 49 + t) * 1024 + d];
        s += v;
        float tv = v + pos[(t + 1) * 1024 + d];
        split_bf16(tv, th + (t + 1) * 1024 + d, tl + (t + 1) * 1024 + d);
    }
    float cls = s * (1.f / 49.f) + pos[d];
    __nv_bfloat16 ch_, cl_;
    split_bf16(cls, &ch_, &cl_);
    th[d] = ch_; tl[d] = cl_;
    g_clsh[(size_t)img * 1024 + d] = ch_;
    g_clsl[(size_t)img * 1024 + d] = cl_;
}

// ---------------- attention core: scores + softmax + ctx (split out) ----------------
__global__ void k_attn(int dummy) {
    __shared__ float qs[1024];
    __shared__ float sc[50];
    __shared__ float pr[50];
    int img = blockIdx.x, tid = threadIdx.x;   // 256
    for (int i = tid; i < 1024; i += 256) qs[i] = g_q[(size_t)img * 1024 + i];
    __syncthreads();

    int wid = tid >> 5, lid = tid & 31;
    for (int t = wid; t < 50; t += 8) {
        const float* kr = g_k + ((size_t)img * 50 + t) * 1024;
        float s = 0.f;
        for (int d = lid; d < 1024; d += 32) s = fmaf(qs[d], kr[d], s);
#pragma unroll
        for (int o = 16; o > 0; o >>= 1) s += __shfl_xor_sync(0xffffffffu, s, o);
        if (lid == 0) sc[t] = s * 0.03125f;
    }
    __syncthreads();
    if (tid == 0) {
        float mx = -1e30f;
        for (int t = 0; t < 50; t++) mx = fmaxf(mx, sc[t]);
        float sum = 0.f;
        for (int t = 0; t < 50; t++) { float e = expf(sc[t] - mx); pr[t] = e; sum += e; }
        float inv = 1.f / sum;
        for (int t = 0; t < 50; t++) pr[t] *= inv;
    }
    __syncthreads();
    {
        float4 acc = {0.f, 0.f, 0.f, 0.f};
        const float4* v4 = (const float4*)(g_v + (size_t)img * 50 * 1024);
        for (int t = 0; t < 50; t++) {
            float p = pr[t];
            float4 v = v4[t * 256 + tid];
            acc.x = fmaf(p, v.x, acc.x); acc.y = fmaf(p, v.y, acc.y);
            acc.z = fmaf(p, v.z, acc.z); acc.w = fmaf(p, v.w, acc.w);
        }
        size_t o = (size_t)img * 1024 + tid * 4;
        split_bf16(acc.x, g_ctxh + o + 0, g_ctxl + o + 0);
        split_bf16(acc.y, g_ctxh + o + 1, g_ctxl + o + 1);
        split_bf16(acc.z, g_ctxh + o + 2, g_ctxl + o + 2);
        split_bf16(acc.w, g_ctxh + o + 3, g_ctxl + o + 3);
    }
}

// ---------------- momentum fusion ----------------
__global__ void k_fuse(const float* __restrict__ bdd,
                       const float* __restrict__ mom_p,
                       float* __restrict__ out) {
    int n = blockIdx.x, d = threadIdx.x;
    float mom = *mom_p;
    float e = bdd[d];
    const int order[6] = {2, 0, 1, 5, 3, 4};
#pragma unroll
    for (int i = 0; i < 6; i++) {
        int c = order[i];
        if (g_valid[n * 6 + c])
            e = mom * e + (1.f - mom) * g_emb[((size_t)(n * 6 + c)) * 1024 + d];
    }
    out[(size_t)n * 1024 + d] = e;
}

// ---------------- launch ----------------
extern "C" void kernel_launch(void* const* d_in, const int* in_sizes, int n_in,
                              void* d_out, int out_size) {
    const float* camera_imgs = (const float*)d_in[0];
    const float* pred_boxes  = (const float*)d_in[1];
    const float* img_aug     = (const float*)d_in[2];
    const float* lidar_aug   = (const float*)d_in[3];
    const float* l2i         = (const float*)d_in[4];
    const float* momentum    = (const float*)d_in[5];
    const float* bdd         = (const float*)d_in[6];
    const float* theta_w     = (const float*)d_in[7];
    const float* theta_b     = (const float*)d_in[8];
    const float* conv1       = (const float*)d_in[9];
    const float* conv2       = (const float*)d_in[10];
    const float* conv3       = (const float*)d_in[11];
    const float* pos         = (const float*)d_in[12];
    const float* wq          = (const float*)d_in[13];
    const float* wk          = (const float*)d_in[14];
    const float* wv          = (const float*)d_in[15];
    const float* wo          = (const float*)d_in[16];

    const int TG_SMEM = 2 * STG_BYTES;   // 81920
    const int C1_SMEM = 2 * STG64;       // 102400
    static int smem_set = 0;
    if (!smem_set) {
        cudaFuncSetAttribute(k_tgemm, cudaFuncAttributeMaxDynamicSharedMemorySize, TG_SMEM);
        cudaFuncSetAttribute(k_tgemm_c1, cudaFuncAttributeMaxDynamicSharedMemorySize, C1_SMEM);
        smem_set = 1;
    }

    __nv_bfloat16 *w2h, *w2l, *w3h, *w3l;
    __nv_bfloat16 *wqth, *wqtl, *wkth, *wktl, *wvth, *wvtl, *woth, *wotl;
    __nv_bfloat16 *b2h, *b2l, *b3h, *b3l, *tokh, *tokl;
    __nv_bfloat16 *clsh, *clsl, *ctxh, *ctxl, *h2h, *h2l;
    float *h3n, *gq, *gk, *gv, *gemb;
    cudaGetSymbolAddress((void**)&w2h, g_w2h);  cudaGetSymbolAddress((void**)&w2l, g_w2l);
    cudaGetSymbolAddress((void**)&w3h, g_w3h);  cudaGetSymbolAddress((void**)&w3l, g_w3l);
    cudaGetSymbolAddress((void**)&wqth, g_wqth); cudaGetSymbolAddress((void**)&wqtl, g_wqtl);
    cudaGetSymbolAddress((void**)&wkth, g_wkth); cudaGetSymbolAddress((void**)&wktl, g_wktl);
    cudaGetSymbolAddress((void**)&wvth, g_wvth); cudaGetSymbolAddress((void**)&wvtl, g_wvtl);
    cudaGetSymbolAddress((void**)&woth, g_woth); cudaGetSymbolAddress((void**)&wotl, g_wotl);
    cudaGetSymbolAddress((void**)&b2h, g_b2h);  cudaGetSymbolAddress((void**)&b2l, g_b2l);
    cudaGetSymbolAddress((void**)&b3h, g_b3h);  cudaGetSymbolAddress((void**)&b3l, g_b3l);
    cudaGetSymbolAddress((void**)&tokh, g_tokh); cudaGetSymbolAddress((void**)&tokl, g_tokl);
    cudaGetSymbolAddress((void**)&clsh, g_clsh); cudaGetSymbolAddress((void**)&clsl, g_clsl);
    cudaGetSymbolAddress((void**)&ctxh, g_ctxh); cudaGetSymbolAddress((void**)&ctxl, g_ctxl);
    cudaGetSymbolAddress((void**)&h2h, g_h2h);  cudaGetSymbolAddress((void**)&h2l, g_h2l);
    cudaGetSymbolAddress((void**)&h3n, g_h3n);
    cudaGetSymbolAddress((void**)&gq, g_q);     cudaGetSymbolAddress((void**)&gemb, g_emb);
    cudaGetSymbolAddress((void**)&gk, g_k);     cudaGetSymbolAddress((void**)&gv, g_v);

    k_setup<<<(NIMG + 127) / 128, 128>>>(pred_boxes, lidar_aug, l2i, img_aug, theta_w, theta_b);
    k_zero_crop_halo<<<(NIMG * 1824 + 255) / 256, 256>>>();
    k_sample<<<dim3((CROP_ * CROP_ + 255) / 256, NIMG), 256>>>(camera_imgs);

    k_cvt_w1<<<(64 * K1P + 255) / 256, 256>>>(conv1);
    k_cvt_w2<<<(256 * 576 + 255) / 256, 256>>>(conv2);
    k_cvt_w3<<<(1024 * 2304 + 255) / 256, 256>>>(conv3);
    k_cvt_wt<<<(1024 * 1024) / 256, 256>>>(wq, wqth, wqtl);
    k_cvt_wt<<<(1024 * 1024) / 256, 256>>>(wk, wkth, wktl);
    k_cvt_wt<<<(1024 * 1024) / 256, 256>>>(wv, wvth, wvtl);
    k_cvt_wt<<<(1024 * 1024) / 256, 256>>>(wo, woth, wotl);

    // conv1: fused im2col GEMM -> h1 split
    k_tgemm_c1<<<N1 / 256, 256, C1_SMEM>>>();

    // conv2 -> split h2  (grid: m fast, n slow for B L2 reuse)
    k_im2col2<<<(NIMG * 196 * 72 + 255) / 256, 256>>>();
    k_tgemm<<<dim3(2, 588), 256, TG_SMEM>>>(w2h, w2l, b2h, b2l, 576, 256, nullptr, h2h, h2l, 2);

    // conv3 -> fp32 h3
    k_im2col3<<<(NIMG * 49 * 288 + 255) / 256, 256>>>();
    k_tgemm<<<dim3(8, 147), 256, TG_SMEM>>>(w3h, w3l, b3h, b3l, 2304, 1024, h3n, nullptr, nullptr, 1);

    k_tokens<<<NIMG, 1024>>>(pos);

    // q projection (CLS only), K/V projections
    k_tgemm<<<dim3(8, 3), 256, TG_SMEM>>>(wqth, wqtl, clsh, clsl, 1024, 1024, gq, nullptr, nullptr, 0);
    k_tgemm<<<dim3(8, 150), 256, TG_SMEM>>>(wkth, wktl, tokh, tokl, 1024, 1024, gk, nullptr, nullptr, 0);
    k_tgemm<<<dim3(8, 150), 256, TG_SMEM>>>(wvth, wvtl, tokh, tokl, 1024, 1024, gv, nullptr, nullptr, 0);

    k_attn<<<NIMG, 256>>>(0);

    // output projection
    k_tgemm<<<dim3(8, 3), 256, TG_SMEM>>>(woth, wotl, ctxh, ctxl, 1024, 1024, gemb, nullptr, nullptr, 0);

    k_fuse<<<NBOX, 1024>>>(bdd, momentum, (float*)d_out);
}